// round 11
// baseline (speedup 1.0000x reference)
#include <cuda_runtime.h>
#include <cuda_bf16.h>

// dRMSD, L=2048, B=8 — single fused kernel.
// R11 = R10 (bf16x2 Gram hot loop) + MUFU offload: per 2-pair GROUP, one
// sqrt on MUFU, one via 2x-Newton rsqrt (quake seed on alu pipe + 8 fma ops).
// Hypothesis: MUFU is a per-SM shared unit (~8 cyc/op/SM) and has been the
// invariant wall across R3-R10 (1 sqrt/pair each round, all ~19us).

#define BATCH  8
#define NPTS   2047
#define NPAD   2048
#define TS     128
#define NT     (NPAD / TS)                 // 16
#define TPAIRS (NT * (NT + 1) / 2)         // 136
#define NBLK   (BATCH * TPAIRS)            // 1088
#define TPB    128

__device__ float    g_part[NBLK];
__device__ float    g_aux[BATCH][NT][9];   // S|x|^2, Sx(3), S|y|^2, Sy(3), S|x||y|
__device__ unsigned g_count;               // zero-init; reset by last block

__device__ __forceinline__ float sqrt_abs(float x) {
    float r; asm("sqrt.approx.f32 %0, %1;" : "=f"(r) : "f"(fabsf(x))); return r;
}
__device__ __forceinline__ __nv_bfloat162 u2b(unsigned u) {
    __nv_bfloat162 r; *reinterpret_cast<unsigned*>(&r) = u; return r;
}
__device__ __forceinline__ unsigned b2u(__nv_bfloat162 v) {
    return *reinterpret_cast<unsigned*>(&v);
}

__global__ __launch_bounds__(TPB, 6) void drmsd_kernel(
    const float* __restrict__ x, const float* __restrict__ y,
    float* __restrict__ out)
{
    int bid = blockIdx.x;
    int b = bid / TPAIRS;
    int t = bid - b * TPAIRS;
    // closed-form triangular decode: 1089 - 8*S(k) = (33-2k)^2
    int ti = (int)((33.0f - sqrtf((float)(1089 - 8 * t))) * 0.5f);
    if (ti * (33 - ti) / 2 > t) ti--;
    if ((ti + 1) * (33 - (ti + 1)) / 2 <= t) ti++;
    int tj = ti + (t - ti * (33 - ti) / 2);
    bool diag = (ti == tj);

    // si: raw fp32 i coords + norms; sjh: bf16 operands (-2*coords, norms)
    __shared__ __align__(16) float si[8][TS];
    __shared__ __align__(16) __nv_bfloat16 sjh[8][TS];
    int tid = threadIdx.x;

    // ---- load i-point (one per thread) ----
    float ix0 = 0.f, ix1 = 0.f, ix2 = 0.f, iy0 = 0.f, iy1 = 0.f, iy2 = 0.f;
    {
        int s = ti * TS + tid;
        if (s < NPTS) {
            int base = ((s + 1) * BATCH + b) * 3;
            ix0 = x[base]; ix1 = x[base + 1]; ix2 = x[base + 2];
            iy0 = y[base]; iy1 = y[base + 1]; iy2 = y[base + 2];
        }
    }
    float ipx = ix0 * ix0 + ix1 * ix1 + ix2 * ix2;
    float ipy = iy0 * iy0 + iy1 * iy1 + iy2 * iy2;
    si[0][tid] = ix0; si[1][tid] = ix1; si[2][tid] = ix2; si[3][tid] = ipx;
    si[4][tid] = iy0; si[5][tid] = iy1; si[6][tid] = iy2; si[7][tid] = ipy;

    // ---- load j-point (one per thread), store bf16 hot-loop operands ----
    {
        int s = tj * TS + tid;
        float jx0 = 0.f, jx1 = 0.f, jx2 = 0.f, jy0 = 0.f, jy1 = 0.f, jy2 = 0.f;
        if (s < NPTS) {
            int base = ((s + 1) * BATCH + b) * 3;
            jx0 = x[base]; jx1 = x[base + 1]; jx2 = x[base + 2];
            jy0 = y[base]; jy1 = y[base + 1]; jy2 = y[base + 2];
        }
        sjh[0][tid] = __float2bfloat16(-2.f * jx0);
        sjh[1][tid] = __float2bfloat16(-2.f * jx1);
        sjh[2][tid] = __float2bfloat16(-2.f * jx2);
        sjh[3][tid] = __float2bfloat16(jx0 * jx0 + jx1 * jx1 + jx2 * jx2);
        sjh[4][tid] = __float2bfloat16(-2.f * jy0);
        sjh[5][tid] = __float2bfloat16(-2.f * jy1);
        sjh[6][tid] = __float2bfloat16(-2.f * jy2);
        sjh[7][tid] = __float2bfloat16(jy0 * jy0 + jy1 * jy1 + jy2 * jy2);
    }
    __syncthreads();

    // ---- per-tile moments in fp32 (diagonal blocks only) ----
    if (diag) {
        float v[9] = { ipx, ix0, ix1, ix2, ipy, iy0, iy1, iy2, sqrtf(ipx * ipy) };
        #pragma unroll
        for (int off = 16; off > 0; off >>= 1)
            #pragma unroll
            for (int q = 0; q < 9; q++)
                v[q] += __shfl_down_sync(0xffffffffu, v[q], off);
        __shared__ float waux[TPB / 32][9];
        if ((tid & 31) == 0)
            #pragma unroll
            for (int q = 0; q < 9; q++) waux[tid >> 5][q] = v[q];
        __syncthreads();
        if (tid == 0)
            #pragma unroll
            for (int q = 0; q < 9; q++)
                g_aux[b][ti][q] = waux[0][q] + waux[1][q] + waux[2][q] + waux[3][q];
    }

    // ---- hot loop: 2 i per lane, warp-split j halves, bf16x2 math ----
    int w = tid >> 5, lane = tid & 31;
    int jbase = (w & 1) * 64;              // warp's j half (64 j's)
    int i0 = (w >> 1) * 64 + lane;         // first i
    int i1 = i0 + 32;                      // second i

    __nv_bfloat162 X00 = __float2bfloat162_rn(si[0][i0]);
    __nv_bfloat162 X01 = __float2bfloat162_rn(si[1][i0]);
    __nv_bfloat162 X02 = __float2bfloat162_rn(si[2][i0]);
    __nv_bfloat162 PX0 = __float2bfloat162_rn(si[3][i0]);
    __nv_bfloat162 Y00 = __float2bfloat162_rn(si[4][i0]);
    __nv_bfloat162 Y01 = __float2bfloat162_rn(si[5][i0]);
    __nv_bfloat162 Y02 = __float2bfloat162_rn(si[6][i0]);
    __nv_bfloat162 PY0 = __float2bfloat162_rn(si[7][i0]);
    __nv_bfloat162 X10 = __float2bfloat162_rn(si[0][i1]);
    __nv_bfloat162 X11 = __float2bfloat162_rn(si[1][i1]);
    __nv_bfloat162 X12 = __float2bfloat162_rn(si[2][i1]);
    __nv_bfloat162 PX1 = __float2bfloat162_rn(si[3][i1]);
    __nv_bfloat162 Y10 = __float2bfloat162_rn(si[4][i1]);
    __nv_bfloat162 Y11 = __float2bfloat162_rn(si[5][i1]);
    __nv_bfloat162 Y12 = __float2bfloat162_rn(si[6][i1]);
    __nv_bfloat162 PY1 = __float2bfloat162_rn(si[7][i1]);

    float a00 = 0.f, a01 = 0.f, a10 = 0.f, a11 = 0.f;

    // one GROUP = 1 i vs 2 j's. lo pair -> MUFU sqrt; hi pair -> 2-NR rsqrt
    // (quake seed; p=0 safe: 0 * finite = 0). Splits the sqrt load between
    // the MUFU unit and the fma pipe.
    #define GROUP(CW0, CW1, CW2, CWN, DW0, DW1, DW2, DWN, XX0, XX1, XX2, PPX, YY0, YY1, YY2, PPY, S0, S1) { \
        __nv_bfloat162 tx_ = __hfma2(u2b(CW0), XX0, __hfma2(u2b(CW1), XX1,      \
                              __hfma2(u2b(CW2), XX2, __hadd2(u2b(CWN), PPX))));   \
        __nv_bfloat162 ty_ = __hfma2(u2b(DW0), YY0, __hfma2(u2b(DW1), YY1,      \
                              __hfma2(u2b(DW2), YY2, __hadd2(u2b(DWN), PPY))));   \
        unsigned pv_ = b2u(__hmul2(tx_, ty_));                                   \
        S0 += sqrt_abs(__uint_as_float(pv_ << 16));        /* lo: MUFU */        \
        unsigned pb_ = pv_ & 0x7fff0000u;                  /* hi: |p| bits */    \
        float pf_ = __uint_as_float(pb_);                                        \
        float y0_ = __uint_as_float(0x5f3759dfu - (pb_ >> 1));                   \
        float ph_ = 0.5f * pf_;                                                  \
        float t_  = ph_ * y0_;                                                   \
        float u_  = fmaf(t_, y0_, -1.5f);                                        \
        float y1_ = -y0_ * u_;                                                   \
        float t2_ = ph_ * y1_;                                                   \
        float u2_ = fmaf(t2_, y1_, -1.5f);                                       \
        float y2_ = -y1_ * u2_;                                                  \
        S1 = fmaf(pf_, y2_, S1);                          /* sqrt = p*rsqrt */   \
    }

    #pragma unroll 2
    for (int jc = 0; jc < 8; jc++) {       // 8 j's per iteration
        int jo = jbase + jc * 8;           // warp-uniform -> LDS broadcast
        uint4 c0 = *reinterpret_cast<const uint4*>(&sjh[0][jo]);  // 4 bf16x2
        uint4 c1 = *reinterpret_cast<const uint4*>(&sjh[1][jo]);
        uint4 c2 = *reinterpret_cast<const uint4*>(&sjh[2][jo]);
        uint4 cn = *reinterpret_cast<const uint4*>(&sjh[3][jo]);
        uint4 d0 = *reinterpret_cast<const uint4*>(&sjh[4][jo]);
        uint4 d1 = *reinterpret_cast<const uint4*>(&sjh[5][jo]);
        uint4 d2 = *reinterpret_cast<const uint4*>(&sjh[6][jo]);
        uint4 dn = *reinterpret_cast<const uint4*>(&sjh[7][jo]);

        GROUP(c0.x, c1.x, c2.x, cn.x, d0.x, d1.x, d2.x, dn.x,
              X00, X01, X02, PX0, Y00, Y01, Y02, PY0, a00, a01)
        GROUP(c0.x, c1.x, c2.x, cn.x, d0.x, d1.x, d2.x, dn.x,
              X10, X11, X12, PX1, Y10, Y11, Y12, PY1, a10, a11)
        GROUP(c0.y, c1.y, c2.y, cn.y, d0.y, d1.y, d2.y, dn.y,
              X00, X01, X02, PX0, Y00, Y01, Y02, PY0, a00, a01)
        GROUP(c0.y, c1.y, c2.y, cn.y, d0.y, d1.y, d2.y, dn.y,
              X10, X11, X12, PX1, Y10, Y11, Y12, PY1, a10, a11)
        GROUP(c0.z, c1.z, c2.z, cn.z, d0.z, d1.z, d2.z, dn.z,
              X00, X01, X02, PX0, Y00, Y01, Y02, PY0, a00, a01)
        GROUP(c0.z, c1.z, c2.z, cn.z, d0.z, d1.z, d2.z, dn.z,
              X10, X11, X12, PX1, Y10, Y11, Y12, PY1, a10, a11)
        GROUP(c0.w, c1.w, c2.w, cn.w, d0.w, d1.w, d2.w, dn.w,
              X00, X01, X02, PX0, Y00, Y01, Y02, PY0, a00, a01)
        GROUP(c0.w, c1.w, c2.w, cn.w, d0.w, d1.w, d2.w, dn.w,
              X10, X11, X12, PX1, Y10, Y11, Y12, PY1, a10, a11)
    }
    #undef GROUP

    float val = (a00 + a01) + (a10 + a11);

    // deterministic block reduce
    #pragma unroll
    for (int off = 16; off > 0; off >>= 1)
        val += __shfl_down_sync(0xffffffffu, val, off);
    __shared__ float wsum[TPB / 32];
    if ((tid & 31) == 0) wsum[tid >> 5] = val;
    __syncthreads();
    if (tid == 0) {
        float s = wsum[0] + wsum[1] + wsum[2] + wsum[3];
        g_part[bid] = diag ? s : 2.0f * s;
    }

    // ---- last-block final reduction ----
    __shared__ bool isLast;
    if (tid == 0) {
        __threadfence();
        unsigned v = atomicAdd(&g_count, 1u);
        isLast = (v == (unsigned)(gridDim.x - 1));
    }
    __syncthreads();
    if (!isLast) return;
    __threadfence();

    int b2 = tid >> 4;                  // 0..7
    int l  = tid & 15;                  // 0..15

    float wacc = 0.f;
    for (int k = l; k < TPAIRS; k += 16)
        wacc += g_part[b2 * TPAIRS + k];
    float a[9];
    #pragma unroll
    for (int q = 0; q < 9; q++) a[q] = g_aux[b2][l][q];

    #pragma unroll
    for (int off = 8; off > 0; off >>= 1) {
        wacc += __shfl_down_sync(0xffffffffu, wacc, off, 16);
        #pragma unroll
        for (int q = 0; q < 9; q++)
            a[q] += __shfl_down_sync(0xffffffffu, a[q], off, 16);
    }

    __shared__ float norms[BATCH];
    if (l == 0) {
        float n = (float)NPTS;
        float T = 2.0f * (n * a[0] - (a[1] * a[1] + a[2] * a[2] + a[3] * a[3]))
                + 2.0f * (n * a[4] - (a[5] * a[5] + a[6] * a[6] + a[7] * a[7]));
        float W = wacc - 2.0f * a[8];   // remove pad-point pairs
        float S = T - 2.0f * W;
        if (S < 0.f) S = 0.f;
        norms[b2] = sqrtf(S);
    }
    __syncthreads();
    if (tid == 0) {
        float tot = 0.f;
        #pragma unroll
        for (int i = 0; i < BATCH; i++) tot += norms[i];
        float n = (float)NPTS;
        out[0] = tot / sqrtf(n * n - n) / (float)BATCH;
        g_count = 0;                    // reset for graph replay
    }
}

extern "C" void kernel_launch(void* const* d_in, const int* in_sizes, int n_in,
                              void* d_out, int out_size) {
    const float* x = (const float*)d_in[0];
    const float* y = (const float*)d_in[1];
    (void)in_sizes; (void)n_in; (void)out_size;
    drmsd_kernel<<<NBLK, TPB>>>(x, y, (float*)d_out);
}

// round 12
// speedup vs baseline: 1.0181x; 1.0181x over previous
#include <cuda_runtime.h>
#include <cuda_bf16.h>

// dRMSD, L=2048, B=8.
// R12 = R10 bf16x2 hot loop + COALESCED memory path:
//   prep kernel pre-transposes (L,B,3) -> per-batch bf16 operand arrays via
//   smem staging (all global reads coalesced float4). Main-kernel tile loads
//   become 1 LDG.128 per thread (j) + coalesced LDG.16 (i) instead of
//   ~24-line gathers per warp LDG.
// Diagonal blocks still read exact fp32 from x,y for the moments (T term
// must be exact; bf16 moments would be amplified x13 by the T-2W cancel).

#define BATCH  8
#define NPTS   2047
#define NPAD   2048
#define TS     128
#define NT     (NPAD / TS)                 // 16
#define TPAIRS (NT * (NT + 1) / 2)         // 136
#define NBLK   (BATCH * TPAIRS)            // 1088
#define TPB    128

// operand arrays (device globals zero-init once; pad slot s=2047 never written)
__device__ __align__(16) __nv_bfloat16 g_jb[BATCH][8][NPAD]; // -2x(3),|x|^2,-2y(3),|y|^2
__device__ __align__(16) __nv_bfloat16 g_ib[BATCH][8][NPAD]; //   x(3),|x|^2,  y(3),|y|^2
__device__ float    g_part[NBLK];
__device__ float    g_aux[BATCH][NT][9];
__device__ unsigned g_count;

__device__ __forceinline__ float sqrt_abs(float x) {
    float r; asm("sqrt.approx.f32 %0, %1;" : "=f"(r) : "f"(fabsf(x))); return r;
}
__device__ __forceinline__ __nv_bfloat162 u2b(unsigned u) {
    __nv_bfloat162 r; *reinterpret_cast<unsigned*>(&r) = u; return r;
}
__device__ __forceinline__ unsigned b2u(__nv_bfloat162 v) {
    return *reinterpret_cast<unsigned*>(&v);
}

// ---------------- prep: coalesced transpose + operand precompute ------------
#define PREP_T 384
__global__ __launch_bounds__(PREP_T) void prep_kernel(
    const float* __restrict__ x, const float* __restrict__ y)
{
    __shared__ float sx[1536], sy[1536];   // 64 rows x 8 batches x 3 coords
    int r0 = blockIdx.x * 64;              // 32 blocks cover 2048 rows
    int tid = threadIdx.x;

    // fully coalesced staging: 384 float4 = 1536 floats per tensor
    reinterpret_cast<float4*>(sx)[tid] =
        reinterpret_cast<const float4*>(x + r0 * 24)[tid];
    reinterpret_cast<float4*>(sy)[tid] =
        reinterpret_cast<const float4*>(y + r0 * 24)[tid];
    __syncthreads();

    for (int p = tid; p < 512; p += PREP_T) {   // 64 rows x 8 batches
        int b  = p >> 6;
        int rl = p & 63;
        int row = r0 + rl;
        if (row < 1) continue;                  // row 0 dropped by the mask
        int s = row - 1;                        // gathered index 0..2046
        int o = (rl * 8 + b) * 3;
        float x0 = sx[o], x1 = sx[o + 1], x2 = sx[o + 2];
        float y0 = sy[o], y1 = sy[o + 1], y2 = sy[o + 2];
        float px = x0 * x0 + x1 * x1 + x2 * x2;
        float py = y0 * y0 + y1 * y1 + y2 * y2;
        g_jb[b][0][s] = __float2bfloat16(-2.f * x0);
        g_jb[b][1][s] = __float2bfloat16(-2.f * x1);
        g_jb[b][2][s] = __float2bfloat16(-2.f * x2);
        g_jb[b][3][s] = __float2bfloat16(px);
        g_jb[b][4][s] = __float2bfloat16(-2.f * y0);
        g_jb[b][5][s] = __float2bfloat16(-2.f * y1);
        g_jb[b][6][s] = __float2bfloat16(-2.f * y2);
        g_jb[b][7][s] = __float2bfloat16(py);
        g_ib[b][0][s] = __float2bfloat16(x0);
        g_ib[b][1][s] = __float2bfloat16(x1);
        g_ib[b][2][s] = __float2bfloat16(x2);
        g_ib[b][3][s] = __float2bfloat16(px);
        g_ib[b][4][s] = __float2bfloat16(y0);
        g_ib[b][5][s] = __float2bfloat16(y1);
        g_ib[b][6][s] = __float2bfloat16(y2);
        g_ib[b][7][s] = __float2bfloat16(py);
    }
}

// ---------------- main ------------------------------------------------------
__global__ __launch_bounds__(TPB, 6) void drmsd_kernel(
    const float* __restrict__ x, const float* __restrict__ y,
    float* __restrict__ out)
{
    int bid = blockIdx.x;
    int b = bid / TPAIRS;
    int t = bid - b * TPAIRS;
    int ti = (int)((33.0f - sqrtf((float)(1089 - 8 * t))) * 0.5f);
    if (ti * (33 - ti) / 2 > t) ti--;
    if ((ti + 1) * (33 - (ti + 1)) / 2 <= t) ti++;
    int tj = ti + (t - ti * (33 - ti) / 2);
    bool diag = (ti == tj);

    __shared__ __align__(16) __nv_bfloat16 sjh[8][TS];
    int tid = threadIdx.x;

    // ---- j-tile: one coalesced LDG.128 + STS.128 per thread ----
    {
        int ch  = tid >> 4;                // 0..7
        int t16 = tid & 15;                // 0..15 (16B each = 256B/channel)
        const uint4* src = reinterpret_cast<const uint4*>(&g_jb[b][ch][tj * TS]);
        reinterpret_cast<uint4*>(&sjh[ch][0])[t16] = src[t16];
    }

    // ---- per-tile moments (diagonal blocks only; exact fp32 path) ----
    if (diag) {
        float ix0 = 0.f, ix1 = 0.f, ix2 = 0.f, iy0 = 0.f, iy1 = 0.f, iy2 = 0.f;
        int s = ti * TS + tid;
        if (s < NPTS) {
            int base = ((s + 1) * BATCH + b) * 3;
            ix0 = x[base]; ix1 = x[base + 1]; ix2 = x[base + 2];
            iy0 = y[base]; iy1 = y[base + 1]; iy2 = y[base + 2];
        }
        float ipx = ix0 * ix0 + ix1 * ix1 + ix2 * ix2;
        float ipy = iy0 * iy0 + iy1 * iy1 + iy2 * iy2;
        float v[9] = { ipx, ix0, ix1, ix2, ipy, iy0, iy1, iy2, sqrtf(ipx * ipy) };
        #pragma unroll
        for (int off = 16; off > 0; off >>= 1)
            #pragma unroll
            for (int q = 0; q < 9; q++)
                v[q] += __shfl_down_sync(0xffffffffu, v[q], off);
        __shared__ float waux[TPB / 32][9];
        if ((tid & 31) == 0)
            #pragma unroll
            for (int q = 0; q < 9; q++) waux[tid >> 5][q] = v[q];
        __syncthreads();
        if (tid == 0)
            #pragma unroll
            for (int q = 0; q < 9; q++)
                g_aux[b][ti][q] = waux[0][q] + waux[1][q] + waux[2][q] + waux[3][q];
    }

    // ---- i-splats: coalesced bf16 loads, duplicated to bf16x2 ----
    int w = tid >> 5, lane = tid & 31;
    int jbase = (w & 1) * 64;
    int s0 = ti * TS + (w >> 1) * 64 + lane;   // first i (global index)
    int s1 = s0 + 32;                           // second i

    __nv_bfloat162 X00 = __bfloat162bfloat162(g_ib[b][0][s0]);
    __nv_bfloat162 X01 = __bfloat162bfloat162(g_ib[b][1][s0]);
    __nv_bfloat162 X02 = __bfloat162bfloat162(g_ib[b][2][s0]);
    __nv_bfloat162 PX0 = __bfloat162bfloat162(g_ib[b][3][s0]);
    __nv_bfloat162 Y00 = __bfloat162bfloat162(g_ib[b][4][s0]);
    __nv_bfloat162 Y01 = __bfloat162bfloat162(g_ib[b][5][s0]);
    __nv_bfloat162 Y02 = __bfloat162bfloat162(g_ib[b][6][s0]);
    __nv_bfloat162 PY0 = __bfloat162bfloat162(g_ib[b][7][s0]);
    __nv_bfloat162 X10 = __bfloat162bfloat162(g_ib[b][0][s1]);
    __nv_bfloat162 X11 = __bfloat162bfloat162(g_ib[b][1][s1]);
    __nv_bfloat162 X12 = __bfloat162bfloat162(g_ib[b][2][s1]);
    __nv_bfloat162 PX1 = __bfloat162bfloat162(g_ib[b][3][s1]);
    __nv_bfloat162 Y10 = __bfloat162bfloat162(g_ib[b][4][s1]);
    __nv_bfloat162 Y11 = __bfloat162bfloat162(g_ib[b][5][s1]);
    __nv_bfloat162 Y12 = __bfloat162bfloat162(g_ib[b][6][s1]);
    __nv_bfloat162 PY1 = __bfloat162bfloat162(g_ib[b][7][s1]);

    __syncthreads();   // sjh ready

    float a00 = 0.f, a01 = 0.f, a10 = 0.f, a11 = 0.f;

    #define GROUP(CW0, CW1, CW2, CWN, DW0, DW1, DW2, DWN, XX0, XX1, XX2, PPX, YY0, YY1, YY2, PPY, S0, S1) { \
        __nv_bfloat162 tx_ = __hfma2(u2b(CW0), XX0, __hfma2(u2b(CW1), XX1,      \
                              __hfma2(u2b(CW2), XX2, __hadd2(u2b(CWN), PPX)))); \
        __nv_bfloat162 ty_ = __hfma2(u2b(DW0), YY0, __hfma2(u2b(DW1), YY1,      \
                              __hfma2(u2b(DW2), YY2, __hadd2(u2b(DWN), PPY)))); \
        unsigned pv_ = b2u(__hmul2(tx_, ty_));                                  \
        S0 += sqrt_abs(__uint_as_float(pv_ << 16));                             \
        S1 += sqrt_abs(__uint_as_float(pv_ & 0xffff0000u));                     \
    }

    #pragma unroll 2
    for (int jc = 0; jc < 8; jc++) {       // 8 j's per iteration
        int jo = jbase + jc * 8;           // warp-uniform -> LDS broadcast
        uint4 c0 = *reinterpret_cast<const uint4*>(&sjh[0][jo]);
        uint4 c1 = *reinterpret_cast<const uint4*>(&sjh[1][jo]);
        uint4 c2 = *reinterpret_cast<const uint4*>(&sjh[2][jo]);
        uint4 cn = *reinterpret_cast<const uint4*>(&sjh[3][jo]);
        uint4 d0 = *reinterpret_cast<const uint4*>(&sjh[4][jo]);
        uint4 d1 = *reinterpret_cast<const uint4*>(&sjh[5][jo]);
        uint4 d2 = *reinterpret_cast<const uint4*>(&sjh[6][jo]);
        uint4 dn = *reinterpret_cast<const uint4*>(&sjh[7][jo]);

        GROUP(c0.x, c1.x, c2.x, cn.x, d0.x, d1.x, d2.x, dn.x,
              X00, X01, X02, PX0, Y00, Y01, Y02, PY0, a00, a01)
        GROUP(c0.x, c1.x, c2.x, cn.x, d0.x, d1.x, d2.x, dn.x,
              X10, X11, X12, PX1, Y10, Y11, Y12, PY1, a10, a11)
        GROUP(c0.y, c1.y, c2.y, cn.y, d0.y, d1.y, d2.y, dn.y,
              X00, X01, X02, PX0, Y00, Y01, Y02, PY0, a00, a01)
        GROUP(c0.y, c1.y, c2.y, cn.y, d0.y, d1.y, d2.y, dn.y,
              X10, X11, X12, PX1, Y10, Y11, Y12, PY1, a10, a11)
        GROUP(c0.z, c1.z, c2.z, cn.z, d0.z, d1.z, d2.z, dn.z,
              X00, X01, X02, PX0, Y00, Y01, Y02, PY0, a00, a01)
        GROUP(c0.z, c1.z, c2.z, cn.z, d0.z, d1.z, d2.z, dn.z,
              X10, X11, X12, PX1, Y10, Y11, Y12, PY1, a10, a11)
        GROUP(c0.w, c1.w, c2.w, cn.w, d0.w, d1.w, d2.w, dn.w,
              X00, X01, X02, PX0, Y00, Y01, Y02, PY0, a00, a01)
        GROUP(c0.w, c1.w, c2.w, cn.w, d0.w, d1.w, d2.w, dn.w,
              X10, X11, X12, PX1, Y10, Y11, Y12, PY1, a10, a11)
    }
    #undef GROUP

    float val = (a00 + a01) + (a10 + a11);

    // deterministic block reduce
    #pragma unroll
    for (int off = 16; off > 0; off >>= 1)
        val += __shfl_down_sync(0xffffffffu, val, off);
    __shared__ float wsum[TPB / 32];
    if ((tid & 31) == 0) wsum[tid >> 5] = val;
    __syncthreads();
    if (tid == 0) {
        float s = wsum[0] + wsum[1] + wsum[2] + wsum[3];
        g_part[bid] = diag ? s : 2.0f * s;
    }

    // ---- last-block final reduction ----
    __shared__ bool isLast;
    if (tid == 0) {
        __threadfence();
        unsigned v = atomicAdd(&g_count, 1u);
        isLast = (v == (unsigned)(gridDim.x - 1));
    }
    __syncthreads();
    if (!isLast) return;
    __threadfence();

    int b2 = tid >> 4;
    int l  = tid & 15;

    float wacc = 0.f;
    for (int k = l; k < TPAIRS; k += 16)
        wacc += g_part[b2 * TPAIRS + k];
    float a[9];
    #pragma unroll
    for (int q = 0; q < 9; q++) a[q] = g_aux[b2][l][q];

    #pragma unroll
    for (int off = 8; off > 0; off >>= 1) {
        wacc += __shfl_down_sync(0xffffffffu, wacc, off, 16);
        #pragma unroll
        for (int q = 0; q < 9; q++)
            a[q] += __shfl_down_sync(0xffffffffu, a[q], off, 16);
    }

    __shared__ float norms[BATCH];
    if (l == 0) {
        float n = (float)NPTS;
        float T = 2.0f * (n * a[0] - (a[1] * a[1] + a[2] * a[2] + a[3] * a[3]))
                + 2.0f * (n * a[4] - (a[5] * a[5] + a[6] * a[6] + a[7] * a[7]));
        float W = wacc - 2.0f * a[8];
        float S = T - 2.0f * W;
        if (S < 0.f) S = 0.f;
        norms[b2] = sqrtf(S);
    }
    __syncthreads();
    if (tid == 0) {
        float tot = 0.f;
        #pragma unroll
        for (int i = 0; i < BATCH; i++) tot += norms[i];
        float n = (float)NPTS;
        out[0] = tot / sqrtf(n * n - n) / (float)BATCH;
        g_count = 0;
    }
}

extern "C" void kernel_launch(void* const* d_in, const int* in_sizes, int n_in,
                              void* d_out, int out_size) {
    const float* x = (const float*)d_in[0];
    const float* y = (const float*)d_in[1];
    (void)in_sizes; (void)n_in; (void)out_size;
    prep_kernel<<<32, PREP_T>>>(x, y);
    drmsd_kernel<<<NBLK, TPB>>>(x, y, (float*)d_out);
}